// round 11
// baseline (speedup 1.0000x reference)
#include <cuda_runtime.h>

// B=256 batches, N=128 neurons, E=4N=512 state dims.
// Output layout: [ydot (B*512 floats)] [J (B*512*512 floats)]
#define NN 128
#define BB 256
#define EE 512

// -------- scratch (__device__ globals; no allocations allowed) --------
__device__ float  g_negGCC[NN * NN];     // -g_C[i][j] / C[j], row-major
__device__ float  g_sumGC;               // sum over all i,j of g_C[i][j]/C[j]
__device__ float4 g_state [BB * NN];     // {dvv, jm, jh, jn} per (b,i)

// -------- streams/events (static init; no device-memory allocation) ----
static cudaStream_t g_sA, g_sB;
static cudaEvent_t  g_eFork, g_eDoneA, g_eDoneB;
static struct _StreamInit {
    _StreamInit() {
        cudaFree(0);
        cudaStreamCreateWithFlags(&g_sA, cudaStreamNonBlocking);
        cudaStreamCreateWithFlags(&g_sB, cudaStreamNonBlocking);
        cudaEventCreateWithFlags(&g_eFork,  cudaEventDisableTiming);
        cudaEventCreateWithFlags(&g_eDoneA, cudaEventDisableTiming);
        cudaEventCreateWithFlags(&g_eDoneB, cudaEventDisableTiming);
    }
} g_streamInit;

// ---------------------------------------------------------------------
// Kernel P: fused prep + HH dynamics + coupling matvec (proven R8 form).
// Grid: BB/2 = 128 blocks x 256 threads; half-block sub handles batch
// b = bx*2 + sub. Stages w = gC*invC once per block; deterministic.
// Side duties: block bx spills row bx of -w; block 0 reduces sumGC.
// ---------------------------------------------------------------------
extern __shared__ float sm[];   // w[NN*NN] | invCs[NN] | Vs[2*NN] | red[256]

__global__ void __launch_bounds__(256)
point_kernel(const float* __restrict__ y,     const float* __restrict__ Ic,
             const float* __restrict__ C,
             const float* __restrict__ g_Na,  const float* __restrict__ E_Na,
             const float* __restrict__ g_K,   const float* __restrict__ E_K,
             const float* __restrict__ g_L,   const float* __restrict__ E_L,
             const float* __restrict__ m_inf, const float* __restrict__ tau_m,
             const float* __restrict__ h_inf, const float* __restrict__ tau_h,
             const float* __restrict__ n_inf, const float* __restrict__ tau_n,
             const float* __restrict__ gC,
             float* __restrict__ ydot) {
    float* w     = sm;                    // [NN*NN]
    float* invCs = sm + NN * NN;          // [NN]
    float* Vs    = invCs + NN;            // [2][NN]
    float* red   = Vs + 2 * NN;           // [256]

    const int tid = threadIdx.x;
    const int i   = tid & 127;
    const int sub = tid >> 7;
    const int b   = blockIdx.x * 2 + sub;

    if (tid < NN) invCs[tid] = 1.f / C[tid];

    float4 yv = reinterpret_cast<const float4*>(y)[b * NN + i];
    float V = yv.x, m = yv.y, h = yv.z, n = yv.w;
    Vs[sub * NN + i] = V;
    __syncthreads();

    float colacc = 0.f;
    #pragma unroll 8
    for (int e = tid; e < NN * NN; e += 256) {
        float v = gC[e] * invCs[e & 127];
        w[e] = v;
        colacc += v;
    }
    __syncthreads();

    if (tid < NN)
        g_negGCC[blockIdx.x * NN + tid] = -w[blockIdx.x * NN + tid];

    if (blockIdx.x == 0) {
        red[tid] = colacc;
        __syncthreads();
        #pragma unroll
        for (int s = 128; s > 0; s >>= 1) {
            if (tid < s) red[tid] += red[tid + s];
            __syncthreads();
        }
        if (tid == 0) g_sumGC = red[0];
    }

    const float* wrow = w + i * NN;
    const float* vsub = Vs + sub * NN;
    float a0 = 0.f, a1 = 0.f, a2 = 0.f, a3 = 0.f;
    #pragma unroll 8
    for (int k = 0; k < NN; k += 4) {
        int j0 = (k + 0 + i) & 127;
        int j1 = (k + 1 + i) & 127;
        int j2 = (k + 2 + i) & 127;
        int j3 = (k + 3 + i) & 127;
        a0 = fmaf(wrow[j0], V - vsub[j0], a0);
        a1 = fmaf(wrow[j1], V - vsub[j1], a1);
        a2 = fmaf(wrow[j2], V - vsub[j2], a2);
        a3 = fmaf(wrow[j3], V - vsub[j3], a3);
    }
    float acc = (a0 + a1) + (a2 + a3);

    const float invC = invCs[i];
    float gna = g_Na[i], gk = g_K[i], gl = g_L[i];
    float m2 = m * m, m3 = m2 * m;
    float n2 = n * n, n3 = n2 * n, n4 = n3 * n;
    float dVNa = V - E_Na[i];
    float dVK  = V - E_K[i];

    float Vdot = invC * (-gna * m3 * h * dVNa - gk * n4 * dVK - gl * (V - E_L[i]) + Ic[b]) + acc;
    float mdot = (m_inf[i] - m) / tau_m[i];
    float hdot = (h_inf[i] - h) / tau_h[i];
    float ndot = (n_inf[i] - n) / tau_n[i];

    reinterpret_cast<float4*>(ydot)[b * NN + i] = make_float4(Vdot, mdot, hdot, ndot);

    float dvv = invC * (-gl - gna * h * m3 - gk * n4);
    float jm  = -invC * 3.f * gna * h * m2 * dVNa;
    float jh  = -invC * gna * m3 * dVNa;
    float jn  = -invC * 4.f * gk * n3 * dVK;
    g_state[b * NN + i] = make_float4(dvv, jm, jh, jn);
}

// ---------------------------------------------------------------------
// Kernel Z: zero-rows of J (comp in {1,2,3}; 384 rows; 201 MB).
// NO dependencies (reads tau inputs directly for the diagonal).
// Proven store structure: 2 float4 stores/thread (b, b+128).
// ---------------------------------------------------------------------
__global__ void __launch_bounds__(256)
fill_zeros_kernel(float* __restrict__ J,
                  const float* __restrict__ tau_m,
                  const float* __restrict__ tau_h,
                  const float* __restrict__ tau_n) {
    const int j    = threadIdx.x & 127;
    const int half = threadIdx.x >> 7;
    const int z    = blockIdx.x * 2 + half;       // 0..383, warp-uniform
    const int i    = z / 3;
    const int c    = z - 3 * i;                   // 0..2
    const int r    = 4 * i + 1 + c;
    const int comp = 1 + c;
    const int b    = blockIdx.y;                  // batches b and b+128

    float4 o = make_float4(0.f, 0.f, 0.f, 0.f);
    if (j == i) {
        const float* tau = (comp == 1) ? tau_m : (comp == 2) ? tau_h : tau_n;
        reinterpret_cast<float*>(&o)[comp] = -1.f / tau[i];
    }

    unsigned idx0 = (unsigned)b * (EE * NN) + (unsigned)r * NN + j;
    unsigned idx1 = idx0 + 128u * (EE * NN);
    __stcs(reinterpret_cast<float4*>(J) + idx0, o);
    __stcs(reinterpret_cast<float4*>(J) + idx1, o);
}

// ---------------------------------------------------------------------
// Kernel V: V-rows of J (comp==0; 128 rows; 67 MB). Needs point output.
// Proven store structure: 2 float4 stores/thread (b, b+128).
// ---------------------------------------------------------------------
__global__ void __launch_bounds__(256)
fill_vrows_kernel(float* __restrict__ J) {
    const int j    = threadIdx.x & 127;
    const int half = threadIdx.x >> 7;
    const int i    = blockIdx.x * 2 + half;       // neuron 0..127, warp-uniform
    const int r    = 4 * i;
    const int b    = blockIdx.y;                  // batches b and b+128

    float4 o0 = make_float4(g_negGCC[i * NN + j], 0.f, 0.f, 0.f);
    float4 o1 = o0;

    if (j == i) {
        float s = g_sumGC;
        float4 s0 = g_state[b * NN + i];
        float4 s1 = g_state[(b + 128) * NN + i];
        o0.x += s + s0.x; o0.y = s0.y; o0.z = s0.z; o0.w = s0.w;
        o1.x += s + s1.x; o1.y = s1.y; o1.z = s1.z; o1.w = s1.w;
    }

    unsigned idx0 = (unsigned)b * (EE * NN) + (unsigned)r * NN + j;
    unsigned idx1 = idx0 + 128u * (EE * NN);
    __stcs(reinterpret_cast<float4*>(J) + idx0, o0);
    __stcs(reinterpret_cast<float4*>(J) + idx1, o1);
}

// ---------------------------------------------------------------------
extern "C" void kernel_launch(void* const* d_in, const int* in_sizes, int n_in,
                              void* d_out, int out_size) {
    const float* y     = (const float*)d_in[0];
    const float* Ic    = (const float*)d_in[1];
    const float* C     = (const float*)d_in[2];
    const float* g_Na  = (const float*)d_in[3];
    const float* E_Na  = (const float*)d_in[4];
    const float* g_K   = (const float*)d_in[5];
    const float* E_K   = (const float*)d_in[6];
    const float* g_L   = (const float*)d_in[7];
    const float* E_L   = (const float*)d_in[8];
    const float* m_inf = (const float*)d_in[9];
    const float* tau_m = (const float*)d_in[10];
    const float* h_inf = (const float*)d_in[11];
    const float* tau_h = (const float*)d_in[12];
    const float* n_inf = (const float*)d_in[13];
    const float* tau_n = (const float*)d_in[14];
    const float* g_C   = (const float*)d_in[15];

    float* out  = (float*)d_out;
    float* ydot = out;                       // B*512 floats
    float* J    = out + (size_t)BB * EE;     // B*512*512 floats

    const int smemBytes = (NN * NN + NN + 2 * NN + 256) * sizeof(float);
    cudaFuncSetAttribute(point_kernel,
                         cudaFuncAttributeMaxDynamicSharedMemorySize, smemBytes);

    // Fork both worker streams off the launch stream.
    cudaEventRecord(g_eFork, 0);
    cudaStreamWaitEvent(g_sA, g_eFork, 0);
    cudaStreamWaitEvent(g_sB, g_eFork, 0);

    // Branch A: dependency-free zero rows (201 MB) — streams the whole time.
    fill_zeros_kernel<<<dim3(192, BB / 2), 256, 0, g_sA>>>(J, tau_m, tau_h, tau_n);

    // Branch B: point (latency-bound, ~no BW) then its dependent V rows
    // (67 MB) — runs concurrently with the tail of branch A.
    point_kernel<<<BB / 2, 256, smemBytes, g_sB>>>(
        y, Ic, C, g_Na, E_Na, g_K, E_K, g_L, E_L,
        m_inf, tau_m, h_inf, tau_h, n_inf, tau_n, g_C, ydot);
    fill_vrows_kernel<<<dim3(NN / 2, BB / 2), 256, 0, g_sB>>>(J);

    // Join BOTH branches back into the launch stream.
    cudaEventRecord(g_eDoneA, g_sA);
    cudaEventRecord(g_eDoneB, g_sB);
    cudaStreamWaitEvent(0, g_eDoneA, 0);
    cudaStreamWaitEvent(0, g_eDoneB, 0);
}

// round 13
// speedup vs baseline: 1.4001x; 1.4001x over previous
#include <cuda_runtime.h>

// B=256 batches, N=128 neurons, E=4N=512 state dims.
// Output layout: [ydot (B*512 floats)] [J (B*512*512 floats)]
#define NN 128
#define BB 256
#define EE 512

// -------- scratch (__device__ globals; no allocations allowed) --------
__device__ float g_negInvC[NN];          // -1 / C[j]

// -------- streams/events (static init; no device-memory allocation) ----
static cudaStream_t g_sA, g_sB;
static cudaEvent_t  g_eFork, g_eDoneA, g_eDoneB;
static struct _StreamInit {
    _StreamInit() {
        cudaFree(0);
        cudaStreamCreateWithFlags(&g_sA, cudaStreamNonBlocking);
        cudaStreamCreateWithFlags(&g_sB, cudaStreamNonBlocking);
        cudaEventCreateWithFlags(&g_eFork,  cudaEventDisableTiming);
        cudaEventCreateWithFlags(&g_eDoneA, cudaEventDisableTiming);
        cudaEventCreateWithFlags(&g_eDoneB, cudaEventDisableTiming);
    }
} g_streamInit;

// ---------------------------------------------------------------------
// Kernel T: tiny prep — negInvC table (1 block, 128 threads, ~1us).
// ---------------------------------------------------------------------
__global__ void __launch_bounds__(NN)
tinyprep_kernel(const float* __restrict__ C) {
    g_negInvC[threadIdx.x] = -1.f / C[threadIdx.x];
}

// ---------------------------------------------------------------------
// Kernel P: fused prep + HH dynamics + coupling matvec.
// Grid: BB/2 = 128 blocks x 256 threads; half-block sub = batch bx*2+sub.
// Every block stages the full w = gC*invC tile and tree-reduces its own
// copy of sumGC (fixed order -> deterministic, identical in all blocks).
// Writes ydot AND the J V-diagonal float4s directly (the only bytes of
// J that depend on y; disjoint from fill_all's stores -> no ordering).
// ---------------------------------------------------------------------
extern __shared__ float sm[];   // w[NN*NN] | invCs[NN] | Vs[2*NN] | red[256]

__global__ void __launch_bounds__(256)
point_kernel(const float* __restrict__ y,     const float* __restrict__ Ic,
             const float* __restrict__ C,
             const float* __restrict__ g_Na,  const float* __restrict__ E_Na,
             const float* __restrict__ g_K,   const float* __restrict__ E_K,
             const float* __restrict__ g_L,   const float* __restrict__ E_L,
             const float* __restrict__ m_inf, const float* __restrict__ tau_m,
             const float* __restrict__ h_inf, const float* __restrict__ tau_h,
             const float* __restrict__ n_inf, const float* __restrict__ tau_n,
             const float* __restrict__ gC,
             float* __restrict__ ydot,
             float* __restrict__ J) {
    float* w     = sm;                    // [NN*NN]
    float* invCs = sm + NN * NN;          // [NN]
    float* Vs    = invCs + NN;            // [2][NN]
    float* red   = Vs + 2 * NN;           // [256]

    const int tid = threadIdx.x;
    const int i   = tid & 127;
    const int sub = tid >> 7;
    const int b   = blockIdx.x * 2 + sub;

    if (tid < NN) invCs[tid] = 1.f / C[tid];

    float4 yv = reinterpret_cast<const float4*>(y)[b * NN + i];
    float V = yv.x, m = yv.y, h = yv.z, n = yv.w;
    Vs[sub * NN + i] = V;
    __syncthreads();

    // ---- stage w (fixed order) + per-thread partial for sumGC ----
    float colacc = 0.f;
    #pragma unroll 8
    for (int e = tid; e < NN * NN; e += 256) {
        float v = gC[e] * invCs[e & 127];
        w[e] = v;
        colacc += v;
    }
    __syncthreads();

    // ---- every block: deterministic tree reduce -> local sumGC ----
    red[tid] = colacc;
    __syncthreads();
    #pragma unroll
    for (int s = 128; s > 0; s >>= 1) {
        if (tid < s) red[tid] += red[tid + s];
        __syncthreads();
    }
    const float sumGC = red[0];

    // ---- coupling matvec: staggered conflict-free shared reads ----
    const float* wrow = w + i * NN;
    const float* vsub = Vs + sub * NN;
    float a0 = 0.f, a1 = 0.f, a2 = 0.f, a3 = 0.f;
    #pragma unroll 8
    for (int k = 0; k < NN; k += 4) {
        int j0 = (k + 0 + i) & 127;
        int j1 = (k + 1 + i) & 127;
        int j2 = (k + 2 + i) & 127;
        int j3 = (k + 3 + i) & 127;
        a0 = fmaf(wrow[j0], V - vsub[j0], a0);
        a1 = fmaf(wrow[j1], V - vsub[j1], a1);
        a2 = fmaf(wrow[j2], V - vsub[j2], a2);
        a3 = fmaf(wrow[j3], V - vsub[j3], a3);
    }
    float acc = (a0 + a1) + (a2 + a3);

    const float invC = invCs[i];
    float gna = g_Na[i], gk = g_K[i], gl = g_L[i];
    float m2 = m * m, m3 = m2 * m;
    float n2 = n * n, n3 = n2 * n, n4 = n3 * n;
    float dVNa = V - E_Na[i];
    float dVK  = V - E_K[i];

    float Vdot = invC * (-gna * m3 * h * dVNa - gk * n4 * dVK - gl * (V - E_L[i]) + Ic[b]) + acc;
    float mdot = (m_inf[i] - m) / tau_m[i];
    float hdot = (h_inf[i] - h) / tau_h[i];
    float ndot = (n_inf[i] - n) / tau_n[i];

    reinterpret_cast<float4*>(ydot)[b * NN + i] = make_float4(Vdot, mdot, hdot, ndot);

    // ---- J V-diagonal: {-w_ii + sumGC + dvv, jm, jh, jn} ----
    float dvv = invC * (-gl - gna * h * m3 - gk * n4);
    float jm  = -invC * 3.f * gna * h * m2 * dVNa;
    float jh  = -invC * gna * m3 * dVNa;
    float jn  = -invC * 4.f * gk * n3 * dVK;
    float jvv = dvv + sumGC - w[i * NN + i];

    // float4 index: b*(EE*NN) + (4i)*NN + i = b*65536 + 513*i
    reinterpret_cast<float4*>(J)[(unsigned)b * (EE * NN) + 513u * i] =
        make_float4(jvv, jm, jh, jn);
}

// ---------------------------------------------------------------------
// Kernel F: fill ALL of J (268 MB) except the V-diagonal float4s.
// Proven structure: grid x = 256 row-pairs, y = 128 batch-pairs,
// 256 threads, 2 float4 stores/thread (b, b+128).
//   comp==0 : value = gC[i][j] * negInvC[j]   (both L2-resident)
//             SKIP the j==i store (point writes those bytes).
//   comp>0  : zero except j==i -> -1/tau at slot comp.
// ---------------------------------------------------------------------
__global__ void __launch_bounds__(256)
fill_all_kernel(float* __restrict__ J,
                const float* __restrict__ gC,
                const float* __restrict__ tau_m,
                const float* __restrict__ tau_h,
                const float* __restrict__ tau_n) {
    const int j    = threadIdx.x & 127;
    const int half = threadIdx.x >> 7;
    const int r    = blockIdx.x * 2 + half;       // 0..511, warp-uniform
    const int b    = blockIdx.y;                  // batches b and b+128
    const int comp = r & 3;
    const int i    = r >> 2;

    float4 o = make_float4(0.f, 0.f, 0.f, 0.f);
    if (comp == 0) {
        o.x = gC[i * NN + j] * g_negInvC[j];      // -gC/C, coalesced
    } else if (j == i) {
        const float* tau = (comp == 1) ? tau_m : (comp == 2) ? tau_h : tau_n;
        reinterpret_cast<float*>(&o)[comp] = -1.f / tau[i];
    }

    const bool skip = (comp == 0) & (j == i);     // point owns these bytes
    if (!skip) {
        unsigned idx0 = (unsigned)b * (EE * NN) + (unsigned)r * NN + j;
        unsigned idx1 = idx0 + 128u * (EE * NN);
        __stcs(reinterpret_cast<float4*>(J) + idx0, o);
        __stcs(reinterpret_cast<float4*>(J) + idx1, o);
    }
}

// ---------------------------------------------------------------------
extern "C" void kernel_launch(void* const* d_in, const int* in_sizes, int n_in,
                              void* d_out, int out_size) {
    const float* y     = (const float*)d_in[0];
    const float* Ic    = (const float*)d_in[1];
    const float* C     = (const float*)d_in[2];
    const float* g_Na  = (const float*)d_in[3];
    const float* E_Na  = (const float*)d_in[4];
    const float* g_K   = (const float*)d_in[5];
    const float* E_K   = (const float*)d_in[6];
    const float* g_L   = (const float*)d_in[7];
    const float* E_L   = (const float*)d_in[8];
    const float* m_inf = (const float*)d_in[9];
    const float* tau_m = (const float*)d_in[10];
    const float* h_inf = (const float*)d_in[11];
    const float* tau_h = (const float*)d_in[12];
    const float* n_inf = (const float*)d_in[13];
    const float* tau_n = (const float*)d_in[14];
    const float* g_C   = (const float*)d_in[15];

    float* out  = (float*)d_out;
    float* ydot = out;                       // B*512 floats
    float* J    = out + (size_t)BB * EE;     // B*512*512 floats

    const int smemBytes = (NN * NN + NN + 2 * NN + 256) * sizeof(float);
    cudaFuncSetAttribute(point_kernel,
                         cudaFuncAttributeMaxDynamicSharedMemorySize, smemBytes);

    // Fork both worker streams off the launch stream.
    cudaEventRecord(g_eFork, 0);
    cudaStreamWaitEvent(g_sA, g_eFork, 0);
    cudaStreamWaitEvent(g_sB, g_eFork, 0);

    // Branch A: the single store-heavy kernel (268 MB), preceded only by
    // the 1-block negInvC table.
    tinyprep_kernel<<<1, NN, 0, g_sA>>>(C);
    fill_all_kernel<<<dim3(EE / 2, BB / 2), 256, 0, g_sA>>>(J, g_C, tau_m, tau_h, tau_n);

    // Branch B: latency-bound point — writes ydot + J's V-diagonal bytes
    // (disjoint from branch A's stores; no inter-stream ordering needed).
    point_kernel<<<BB / 2, 256, smemBytes, g_sB>>>(
        y, Ic, C, g_Na, E_Na, g_K, E_K, g_L, E_L,
        m_inf, tau_m, h_inf, tau_h, n_inf, tau_n, g_C, ydot, J);

    // Join BOTH branches back into the launch stream.
    cudaEventRecord(g_eDoneA, g_sA);
    cudaEventRecord(g_eDoneB, g_sB);
    cudaStreamWaitEvent(0, g_eDoneA, 0);
    cudaStreamWaitEvent(0, g_eDoneB, 0);
}

// round 14
// speedup vs baseline: 1.5155x; 1.0824x over previous
#include <cuda_runtime.h>

// B=256 batches, N=128 neurons, E=4N=512 state dims.
// Output layout: [ydot (B*512 floats)] [J (B*512*512 floats)]
#define NN 128
#define BB 256
#define EE 512

// -------- streams/events (static init; no device-memory allocation) ----
static cudaStream_t g_sB;
static cudaEvent_t  g_eFork, g_eDoneB;
static struct _StreamInit {
    _StreamInit() {
        cudaFree(0);
        cudaStreamCreateWithFlags(&g_sB, cudaStreamNonBlocking);
        cudaEventCreateWithFlags(&g_eFork,  cudaEventDisableTiming);
        cudaEventCreateWithFlags(&g_eDoneB, cudaEventDisableTiming);
    }
} g_streamInit;

// ---------------------------------------------------------------------
// Kernel P: fused prep + HH dynamics + coupling matvec, multi-batch
// low-footprint form (32 blocks x 256 threads, 8 batches per block).
// Stages w = gC*invC ONCE per block, tree-reduces its own sumGC (fixed
// order -> deterministic, identical across blocks), then each
// half-block (sub) processes 4 batches. Writes ydot AND the J
// V-diagonal float4s (the only J bytes depending on y; disjoint from
// fill_all's stores -> zero inter-stream ordering needed).
// Only ~32 SMs occupied -> minimal interference with fill_all.
// ---------------------------------------------------------------------
extern __shared__ float sm[];   // w[NN*NN] | invCs[NN] | Vs[2*NN] | red[256]

__global__ void __launch_bounds__(256)
point_kernel(const float* __restrict__ y,     const float* __restrict__ Ic,
             const float* __restrict__ C,
             const float* __restrict__ g_Na,  const float* __restrict__ E_Na,
             const float* __restrict__ g_K,   const float* __restrict__ E_K,
             const float* __restrict__ g_L,   const float* __restrict__ E_L,
             const float* __restrict__ m_inf, const float* __restrict__ tau_m,
             const float* __restrict__ h_inf, const float* __restrict__ tau_h,
             const float* __restrict__ n_inf, const float* __restrict__ tau_n,
             const float* __restrict__ gC,
             float* __restrict__ ydot,
             float* __restrict__ J) {
    float* w     = sm;                    // [NN*NN]
    float* invCs = sm + NN * NN;          // [NN]
    float* Vs    = invCs + NN;            // [2][NN]
    float* red   = Vs + 2 * NN;           // [256]

    const int tid = threadIdx.x;
    const int i   = tid & 127;            // neuron
    const int sub = tid >> 7;             // half-block 0/1

    if (tid < NN) invCs[tid] = 1.f / C[tid];
    __syncthreads();

    // ---- stage w once (fixed order) + partial for sumGC ----
    float colacc = 0.f;
    #pragma unroll 8
    for (int e = tid; e < NN * NN; e += 256) {
        float v = gC[e] * invCs[e & 127];
        w[e] = v;
        colacc += v;
    }
    __syncthreads();

    // ---- deterministic tree reduce -> sumGC (same in every block) ----
    red[tid] = colacc;
    __syncthreads();
    #pragma unroll
    for (int s = 128; s > 0; s >>= 1) {
        if (tid < s) red[tid] += red[tid + s];
        __syncthreads();
    }
    const float sumGC = red[0];

    // ---- per-neuron constants (reused for 4 batches) ----
    const float invC = invCs[i];
    const float gna = g_Na[i], gk = g_K[i], gl = g_L[i];
    const float ena = E_Na[i], ek = E_K[i], el = E_L[i];
    const float mi = m_inf[i], hi = h_inf[i], ni = n_inf[i];
    const float tm = tau_m[i], th = tau_h[i], tn = tau_n[i];
    const float wii = w[i * NN + i];
    const float* wrow = w + i * NN;

    // ---- batch loop: half-block sub handles batches bx*8 + q*2 + sub ----
    for (int q = 0; q < 4; q++) {
        const int b = blockIdx.x * 8 + q * 2 + sub;

        float4 yv = reinterpret_cast<const float4*>(y)[b * NN + i];
        float V = yv.x, m = yv.y, h = yv.z, n = yv.w;

        __syncthreads();                  // Vs free to overwrite
        Vs[sub * NN + i] = V;
        __syncthreads();

        const float* vsub = Vs + sub * NN;
        float a0 = 0.f, a1 = 0.f, a2 = 0.f, a3 = 0.f;
        #pragma unroll 8
        for (int k = 0; k < NN; k += 4) {
            int j0 = (k + 0 + i) & 127;   // staggered: conflict-free banks
            int j1 = (k + 1 + i) & 127;
            int j2 = (k + 2 + i) & 127;
            int j3 = (k + 3 + i) & 127;
            a0 = fmaf(wrow[j0], V - vsub[j0], a0);
            a1 = fmaf(wrow[j1], V - vsub[j1], a1);
            a2 = fmaf(wrow[j2], V - vsub[j2], a2);
            a3 = fmaf(wrow[j3], V - vsub[j3], a3);
        }
        float acc = (a0 + a1) + (a2 + a3);

        float m2 = m * m, m3 = m2 * m;
        float n2 = n * n, n3 = n2 * n, n4 = n3 * n;
        float dVNa = V - ena;
        float dVK  = V - ek;

        float Vdot = invC * (-gna * m3 * h * dVNa - gk * n4 * dVK - gl * (V - el) + Ic[b]) + acc;
        float mdot = (mi - m) / tm;
        float hdot = (hi - h) / th;
        float ndot = (ni - n) / tn;

        reinterpret_cast<float4*>(ydot)[b * NN + i] = make_float4(Vdot, mdot, hdot, ndot);

        // J V-diagonal: {dvv + sumGC - w_ii, jm, jh, jn}
        float dvv = invC * (-gl - gna * h * m3 - gk * n4);
        float jm  = -invC * 3.f * gna * h * m2 * dVNa;
        float jh  = -invC * gna * m3 * dVNa;
        float jn  = -invC * 4.f * gk * n3 * dVK;

        // float4 index: b*(EE*NN) + (4i)*NN + i = b*65536 + 513*i
        reinterpret_cast<float4*>(J)[(unsigned)b * (EE * NN) + 513u * i] =
            make_float4(dvv + sumGC - wii, jm, jh, jn);
    }
}

// ---------------------------------------------------------------------
// Kernel F: fill ALL of J (268 MB) except the V-diagonal float4s.
// ZERO dependencies (reads gC, C, tau inputs directly).
// Proven structure: grid x = 256 row-pairs, y = 128 batch-pairs,
// 256 threads, 2 float4 stores/thread (b, b+128).
//   comp==0 : value = -gC[i][j] / C[j]  (one FDIV per thread; j fixed)
//             SKIP the j==i store (point owns those bytes).
//   comp>0  : zero except j==i -> -1/tau at slot comp.
// ---------------------------------------------------------------------
__global__ void __launch_bounds__(256)
fill_all_kernel(float* __restrict__ J,
                const float* __restrict__ gC,
                const float* __restrict__ C,
                const float* __restrict__ tau_m,
                const float* __restrict__ tau_h,
                const float* __restrict__ tau_n) {
    const int j    = threadIdx.x & 127;
    const int half = threadIdx.x >> 7;
    const int r    = blockIdx.x * 2 + half;       // 0..511, warp-uniform
    const int b    = blockIdx.y;                  // batches b and b+128
    const int comp = r & 3;
    const int i    = r >> 2;

    float4 o = make_float4(0.f, 0.f, 0.f, 0.f);
    if (comp == 0) {
        o.x = -gC[i * NN + j] / C[j];             // L2-resident; 1 FDIV/thread
    } else if (j == i) {
        const float* tau = (comp == 1) ? tau_m : (comp == 2) ? tau_h : tau_n;
        reinterpret_cast<float*>(&o)[comp] = -1.f / tau[i];
    }

    const bool skip = (comp == 0) & (j == i);     // point owns these bytes
    if (!skip) {
        unsigned idx0 = (unsigned)b * (EE * NN) + (unsigned)r * NN + j;
        unsigned idx1 = idx0 + 128u * (EE * NN);
        __stcs(reinterpret_cast<float4*>(J) + idx0, o);
        __stcs(reinterpret_cast<float4*>(J) + idx1, o);
    }
}

// ---------------------------------------------------------------------
extern "C" void kernel_launch(void* const* d_in, const int* in_sizes, int n_in,
                              void* d_out, int out_size) {
    const float* y     = (const float*)d_in[0];
    const float* Ic    = (const float*)d_in[1];
    const float* C     = (const float*)d_in[2];
    const float* g_Na  = (const float*)d_in[3];
    const float* E_Na  = (const float*)d_in[4];
    const float* g_K   = (const float*)d_in[5];
    const float* E_K   = (const float*)d_in[6];
    const float* g_L   = (const float*)d_in[7];
    const float* E_L   = (const float*)d_in[8];
    const float* m_inf = (const float*)d_in[9];
    const float* tau_m = (const float*)d_in[10];
    const float* h_inf = (const float*)d_in[11];
    const float* tau_h = (const float*)d_in[12];
    const float* n_inf = (const float*)d_in[13];
    const float* tau_n = (const float*)d_in[14];
    const float* g_C   = (const float*)d_in[15];

    float* out  = (float*)d_out;
    float* ydot = out;                       // B*512 floats
    float* J    = out + (size_t)BB * EE;     // B*512*512 floats

    const int smemBytes = (NN * NN + NN + 2 * NN + 256) * sizeof(float);
    cudaFuncSetAttribute(point_kernel,
                         cudaFuncAttributeMaxDynamicSharedMemorySize, smemBytes);

    // Fork worker stream B off the capture stream.
    cudaEventRecord(g_eFork, 0);
    cudaStreamWaitEvent(g_sB, g_eFork, 0);

    // Stream B: latency-bound point (32 SMs) — ydot + J V-diagonals.
    point_kernel<<<BB / 8, 256, smemBytes, g_sB>>>(
        y, Ic, C, g_Na, E_Na, g_K, E_K, g_L, E_L,
        m_inf, tau_m, h_inf, tau_h, n_inf, tau_n, g_C, ydot, J);
    cudaEventRecord(g_eDoneB, g_sB);

    // Capture stream: THE store-heavy kernel (268 MB), no dependencies.
    fill_all_kernel<<<dim3(EE / 2, BB / 2), 256>>>(J, g_C, C, tau_m, tau_h, tau_n);

    // Join B back into the capture stream.
    cudaStreamWaitEvent(0, g_eDoneB, 0);
}

// round 15
// speedup vs baseline: 1.5762x; 1.0401x over previous
#include <cuda_runtime.h>

// B=256 batches, N=128 neurons, E=4N=512 state dims.
// Output layout: [ydot (B*512 floats)] [J (B*512*512 floats)]
#define NN 128
#define BB 256
#define EE 512

// ---------------------------------------------------------------------
// ONE kernel, ONE launch. grid = (256, 129), block = 256.
//   blockIdx.y == 0, x <  128 : POINT block for batches {2x, 2x+1}
//   blockIdx.y == 0, x >= 128 : immediate exit
//   blockIdx.y >= 1           : FILL block (proven R14 store structure),
//                               batch pair = y-1, row pair = x.
// Point blocks are first in linear block order -> scheduled in the first
// waves, fully overlapped by the 268 MB fill stream. They write ydot and
// J's V-diagonal float4s -- bytes the fill blocks never touch, so no
// ordering is needed anywhere. All reductions are fixed-order
// (butterfly shfl + shared tree) -> bit-deterministic.
// ---------------------------------------------------------------------
__global__ void __launch_bounds__(256)
hh_fused_kernel(const float* __restrict__ y,     const float* __restrict__ Ic,
                const float* __restrict__ C,
                const float* __restrict__ g_Na,  const float* __restrict__ E_Na,
                const float* __restrict__ g_K,   const float* __restrict__ E_K,
                const float* __restrict__ g_L,   const float* __restrict__ E_L,
                const float* __restrict__ m_inf, const float* __restrict__ tau_m,
                const float* __restrict__ h_inf, const float* __restrict__ tau_h,
                const float* __restrict__ n_inf, const float* __restrict__ tau_n,
                const float* __restrict__ gC,
                float* __restrict__ ydot,
                float* __restrict__ J) {
    // small static smem (3.6 KB) -- used only by point blocks, cheap for all
    __shared__ float invCs[NN];
    __shared__ float Vs   [2 * NN];
    __shared__ float wv0  [NN];
    __shared__ float wv1  [NN];
    __shared__ float rs   [NN];
    __shared__ float red  [NN];

    if (blockIdx.y != 0) {
        // ================= FILL path (proven structure) =================
        const int j    = threadIdx.x & 127;
        const int half = threadIdx.x >> 7;
        const int r    = blockIdx.x * 2 + half;       // 0..511, warp-uniform
        const int b    = blockIdx.y - 1;              // batches b and b+128
        const int comp = r & 3;
        const int i    = r >> 2;

        float4 o = make_float4(0.f, 0.f, 0.f, 0.f);
        if (comp == 0) {
            o.x = -gC[i * NN + j] / C[j];             // L2-resident
        } else if (j == i) {
            const float* tau = (comp == 1) ? tau_m : (comp == 2) ? tau_h : tau_n;
            reinterpret_cast<float*>(&o)[comp] = -1.f / tau[i];
        }

        const bool skip = (comp == 0) & (j == i);     // point owns these bytes
        if (!skip) {
            unsigned idx0 = (unsigned)b * (EE * NN) + (unsigned)r * NN + j;
            unsigned idx1 = idx0 + 128u * (EE * NN);
            __stcs(reinterpret_cast<float4*>(J) + idx0, o);
            __stcs(reinterpret_cast<float4*>(J) + idx1, o);
        }
        return;
    }

    // ==================== POINT path ====================
    if (blockIdx.x >= NN) return;                     // 128 active blocks

    const int tid  = threadIdx.x;
    const int i    = tid & 127;
    const int sub  = tid >> 7;                        // 0/1 -> batch select
    const int lane = tid & 31;
    const int wa   = tid >> 5;                        // warp id 0..7
    const int b0   = blockIdx.x * 2;
    const int b    = b0 + sub;

    if (tid < NN) invCs[tid] = 1.f / C[tid];
    Vs[sub * NN + i] = y[(size_t)b * EE + 4 * i];     // V component only
    __syncthreads();

    // per-lane constants (columns 4*lane .. 4*lane+3), reused for all rows
    const float4 iv = reinterpret_cast<float4*>(invCs)[lane];
    const float4 v0 = reinterpret_cast<float4*>(Vs)[lane];
    const float4 v1 = reinterpret_cast<float4*>(Vs + NN)[lane];

    // warp-per-row GEMV: rows wa*16 .. wa*16+15 ; coalesced float4 gC reads
    #pragma unroll 4
    for (int rr = 0; rr < 16; rr++) {
        const int row = wa * 16 + rr;
        float4 g = reinterpret_cast<const float4*>(gC)[row * 32 + lane];
        float tx = g.x * iv.x, ty = g.y * iv.y, tz = g.z * iv.z, tw = g.w * iv.w;
        float prs = (tx + ty) + (tz + tw);                       // row-sum part
        float pw0 = ((tx * v0.x + ty * v0.y) + (tz * v0.z + tw * v0.w));
        float pw1 = ((tx * v1.x + ty * v1.y) + (tz * v1.z + tw * v1.w));
        #pragma unroll
        for (int s = 16; s > 0; s >>= 1) {                        // bfly, fixed order
            prs += __shfl_xor_sync(0xFFFFFFFFu, prs, s);
            pw0 += __shfl_xor_sync(0xFFFFFFFFu, pw0, s);
            pw1 += __shfl_xor_sync(0xFFFFFFFFu, pw1, s);
        }
        if (lane == 0) { rs[row] = prs; wv0[row] = pw0; wv1[row] = pw1; }
    }
    __syncthreads();

    // sumGC: deterministic shared tree over the 128 row sums
    if (tid < NN) red[tid] = rs[tid];
    __syncthreads();
    #pragma unroll
    for (int s = 64; s > 0; s >>= 1) {
        if (tid < s) red[tid] += red[tid + s];
        __syncthreads();
    }
    const float sumGC = red[0];

    // HH dynamics for (b, i)
    float4 yv = reinterpret_cast<const float4*>(y)[b * NN + i];
    float V = yv.x, m = yv.y, h = yv.z, n = yv.w;

    const float invC = invCs[i];
    const float acc  = V * rs[i] - (sub ? wv1[i] : wv0[i]);   // = sum_j w_ij (V_i - V_j)

    float gna = g_Na[i], gk = g_K[i], gl = g_L[i];
    float m2 = m * m, m3 = m2 * m;
    float n2 = n * n, n3 = n2 * n, n4 = n3 * n;
    float dVNa = V - E_Na[i];
    float dVK  = V - E_K[i];

    float Vdot = invC * (-gna * m3 * h * dVNa - gk * n4 * dVK - gl * (V - E_L[i]) + Ic[b]) + acc;
    float mdot = (m_inf[i] - m) / tau_m[i];
    float hdot = (h_inf[i] - h) / tau_h[i];
    float ndot = (n_inf[i] - n) / tau_n[i];

    reinterpret_cast<float4*>(ydot)[b * NN + i] = make_float4(Vdot, mdot, hdot, ndot);

    // J V-diagonal float4: {dvv + sumGC - w_ii, jm, jh, jn}
    float wii = gC[i * NN + i] * invC;
    float dvv = invC * (-gl - gna * h * m3 - gk * n4);
    float jm  = -invC * 3.f * gna * h * m2 * dVNa;
    float jh  = -invC * gna * m3 * dVNa;
    float jn  = -invC * 4.f * gk * n3 * dVK;

    // float4 index: b*(EE*NN) + (4i)*NN + i = b*65536 + 513*i
    reinterpret_cast<float4*>(J)[(unsigned)b * (EE * NN) + 513u * i] =
        make_float4(dvv + sumGC - wii, jm, jh, jn);
}

// ---------------------------------------------------------------------
extern "C" void kernel_launch(void* const* d_in, const int* in_sizes, int n_in,
                              void* d_out, int out_size) {
    const float* y     = (const float*)d_in[0];
    const float* Ic    = (const float*)d_in[1];
    const float* C     = (const float*)d_in[2];
    const float* g_Na  = (const float*)d_in[3];
    const float* E_Na  = (const float*)d_in[4];
    const float* g_K   = (const float*)d_in[5];
    const float* E_K   = (const float*)d_in[6];
    const float* g_L   = (const float*)d_in[7];
    const float* E_L   = (const float*)d_in[8];
    const float* m_inf = (const float*)d_in[9];
    const float* tau_m = (const float*)d_in[10];
    const float* h_inf = (const float*)d_in[11];
    const float* tau_h = (const float*)d_in[12];
    const float* n_inf = (const float*)d_in[13];
    const float* tau_n = (const float*)d_in[14];
    const float* g_C   = (const float*)d_in[15];

    float* out  = (float*)d_out;
    float* ydot = out;                       // B*512 floats
    float* J    = out + (size_t)BB * EE;     // B*512*512 floats

    // ONE launch: y==0 plane carries the point blocks (scheduled first),
    // y=1..128 planes carry the 268 MB fill.
    hh_fused_kernel<<<dim3(EE / 2, BB / 2 + 1), 256>>>(
        y, Ic, C, g_Na, E_Na, g_K, E_K, g_L, E_L,
        m_inf, tau_m, h_inf, tau_h, n_inf, tau_n, g_C, ydot, J);
}